// round 15
// baseline (speedup 1.0000x reference)
#include <cuda_runtime.h>
#include <cuda_fp16.h>
#include <cstdint>

// ---------------------------------------------------------------- shapes
#define B_   8
#define C_   64
#define H_   96
#define W_   96
#define O_   64
#define K_   9
#define HW_  (H_ * W_)        // 9216
#define Q_   HW_

#define TILE_PX 128
#define NTILES  (B_ * Q_ / TILE_PX)   // 576
#define THREADS 128                   // 4 warps x 32 px each
#define PITCHB  144                   // A row pitch bytes (128 data + 16 pad)
#define ABUF    (128 * PITCHB)        // 18432 per buffer

// ---------------------------------------------------------------- smem map (bytes)
#define SM_BIAS  0                        // float[64]
#define SM_IDX   256                      // uint32[9*128] = 4608
#define SM_WT    4864                     // float4[9*128] = 18432
#define SM_A     23296                    // 2 * 18432 (double buffered)
#define SM_TOTAL (SM_A + 2 * ABUF)        // 60160

// ---------------------------------------------------------------- global scratch
__device__ float g_inT[(size_t)B_ * HW_ * C_];   // NHWC input (~18.9 MB)
__device__ uint4 g_wF[K_ * 4 * 8 * 32];          // B frags [tap][ks][nt][lane]
                                                 // = {bh0, bh1, bl0, bl1}

// ---------------------------------------------------------------- helpers
__device__ __forceinline__ uint32_t smem_u32(const void* p) {
    uint32_t a;
    asm("{ .reg .u64 t; cvta.to.shared.u64 t, %1; cvt.u32.u64 %0, t; }"
        : "=r"(a) : "l"(p));
    return a;
}

// packs: low half = cvt(lo), high half = cvt(hi)
__device__ __forceinline__ uint32_t pack_f16x2(float lo, float hi) {
    uint32_t r;
    asm("cvt.rn.f16x2.f32 %0, %1, %2;" : "=r"(r) : "f"(hi), "f"(lo));
    return r;
}

#define MMA_F16(d, a0, a1, a2, a3, b0, b1)                                    \
    asm volatile(                                                             \
        "mma.sync.aligned.m16n8k16.row.col.f32.f16.f16.f32 "                  \
        "{%0,%1,%2,%3}, {%4,%5,%6,%7}, {%8,%9}, {%0,%1,%2,%3};"               \
        : "+f"((d)[0]), "+f"((d)[1]), "+f"((d)[2]), "+f"((d)[3])              \
        : "r"(a0), "r"(a1), "r"(a2), "r"(a3), "r"(b0), "r"(b1))

#define LDMX4(r0, r1, r2, r3, addr)                                           \
    asm volatile(                                                             \
        "ldmatrix.sync.aligned.m8n8.x4.shared.b16 {%0,%1,%2,%3}, [%4];"       \
        : "=r"(r0), "=r"(r1), "=r"(r2), "=r"(r3) : "r"(addr))

// ---------------------------------------------------------------------------
// Prepass: NCHW -> NHWC input transpose + weight hi/lo fp16 fragment build.
// ---------------------------------------------------------------------------
__global__ __launch_bounds__(256) void prep_kernel(
    const float* __restrict__ in,    // [B][C][H][W]
    const float* __restrict__ wgt)   // [O][C][3][3]
{
    int blk = blockIdx.x;
    if (blk >= B_ * (HW_ / 32)) {                 // 36 weight-fragment blocks
        int idx = (blk - B_ * (HW_ / 32)) * 256 + threadIdx.x;   // 0..9215
        int lane = idx & 31;
        int nt   = (idx >> 5) & 7;
        int ks   = (idx >> 8) & 3;
        int tap  = idx >> 10;
        int n  = nt * 8 + (lane >> 2);
        int c0 = ks * 16 + (lane & 3) * 2;

        float w0 = wgt[n * 576 + (c0)     * 9 + tap];
        float w1 = wgt[n * 576 + (c0 + 1) * 9 + tap];
        float w8 = wgt[n * 576 + (c0 + 8) * 9 + tap];
        float w9 = wgt[n * 576 + (c0 + 9) * 9 + tap];

        float r0 = w0 - __half2float(__float2half_rn(w0));
        float r1 = w1 - __half2float(__float2half_rn(w1));
        float r8 = w8 - __half2float(__float2half_rn(w8));
        float r9 = w9 - __half2float(__float2half_rn(w9));

        uint4 f;
        f.x = pack_f16x2(w0, w1);   // bh0
        f.y = pack_f16x2(w8, w9);   // bh1
        f.z = pack_f16x2(r0, r1);   // bl0
        f.w = pack_f16x2(r8, r9);   // bl1
        g_wF[idx] = f;
        return;
    }
    __shared__ float s[64][33];
    int b   = blk / (HW_ / 32);
    int hw0 = (blk % (HW_ / 32)) * 32;
    for (int i = threadIdx.x; i < 64 * 32; i += 256) {
        int c = i >> 5, hw = i & 31;
        s[c][hw] = in[((size_t)(b * C_ + c)) * HW_ + hw0 + hw];
    }
    __syncthreads();
    for (int i = threadIdx.x; i < 64 * 32; i += 256) {
        int hw = i >> 6, c = i & 63;
        g_inT[((size_t)(b * HW_ + hw0 + hw)) * C_ + c] = s[c][hw];
    }
}

// ---------------------------------------------------------------------------
// Main fused kernel — 4 warps/block, 32 px per warp, warp-synchronous loop
// with DOUBLE-BUFFERED A tile: gather(tap+1) overlaps MMA(tap).
// ---------------------------------------------------------------------------
__global__ __launch_bounds__(128) void dcn_mma_kernel(
    const float* __restrict__ offset,  // [B][18][96][96]
    const float* __restrict__ mask,    // [B][9][96][96]
    const float* __restrict__ bias,    // [64]
    float* __restrict__ out)           // [B][64][96][96]
{
    extern __shared__ char smem[];
    float*    s_bias = (float*)(smem + SM_BIAS);
    uint32_t* s_idx  = (uint32_t*)(smem + SM_IDX);
    float4*   s_wt   = (float4*)(smem + SM_WT);

    const uint32_t sb = smem_u32(smem);
    const int tid  = threadIdx.x;
    const int lane = tid & 31;
    const int wid  = tid >> 5;                           // 0..3
    const int m0   = wid * 32;                           // warp's 32 pixel rows
    const int b     = blockIdx.x / (Q_ / TILE_PX);       // /72
    const int qbase = (blockIdx.x % (Q_ / TILE_PX)) * TILE_PX;

    if (tid < 64) s_bias[tid] = bias[tid];

    const float* Tb = g_inT + (size_t)b * HW_ * C_;

    // ---- Phase 0: per-warp coords, 9 taps x 32 px (1 task/lane/tap) ------
    #pragma unroll
    for (int tap = 0; tap < K_; ++tap) {
        int q  = qbase + m0 + lane;
        int ho = q / W_;
        int wo = q - ho * W_;
        int ky = tap / 3;
        int kx = tap - ky * 3;

        float offy = offset[((size_t)(b * 2 * K_ + 2 * tap)) * Q_ + q];
        float offx = offset[((size_t)(b * 2 * K_ + 2 * tap + 1)) * Q_ + q];
        float m    = mask[((size_t)(b * K_ + tap)) * Q_ + q];

        float y = (float)(ho - 1 + ky) + offy;
        float x = (float)(wo - 1 + kx) + offx;
        float y0f = floorf(y), x0f = floorf(x);
        int y0 = (int)y0f, x0 = (int)x0f;
        int y1 = y0 + 1,   x1 = x0 + 1;
        float wy = y - y0f, wx = x - x0f;

        float vy0 = (y0 >= 0 && y0 < H_) ? 1.0f : 0.0f;
        float vy1 = (y1 >= 0 && y1 < H_) ? 1.0f : 0.0f;
        float vx0 = (x0 >= 0 && x0 < W_) ? 1.0f : 0.0f;
        float vx1 = (x1 >= 0 && x1 < W_) ? 1.0f : 0.0f;

        float w00 = (1.0f - wy) * (1.0f - wx) * m * vy0 * vx0;
        float w01 = (1.0f - wy) * wx          * m * vy0 * vx1;
        float w10 = wy          * (1.0f - wx) * m * vy1 * vx0;
        float w11 = wy          * wx          * m * vy1 * vx1;

        int y0c = min(max(y0, 0), H_ - 1);
        int y1c = min(max(y1, 0), H_ - 1);
        int x0c = min(max(x0, 0), W_ - 1);
        int x1c = min(max(x1, 0), W_ - 1);

        // pack: i00 (14b) | dx<<14 | dy<<15
        uint32_t pk = (uint32_t)(y0c * W_ + x0c)
                    | ((uint32_t)(x1c - x0c) << 14)
                    | ((uint32_t)(y1c - y0c) << 15);

        int e = tap * TILE_PX + m0 + lane;
        s_idx[e] = pk;
        s_wt[e]  = make_float4(w00, w01, w10, w11);
    }
    __syncthreads();   // bias visible (coords are warp-local)

    // fragment accumulators: 2 m-frags x 8 n-tiles x 4 regs
    float acc[2][8][4];
    #pragma unroll
    for (int mf = 0; mf < 2; ++mf)
        #pragma unroll
        for (int nt = 0; nt < 8; ++nt)
            #pragma unroll
            for (int j = 0; j < 4; ++j) acc[mf][nt][j] = 0.0f;

    const int lrow   = (lane & 7) + ((lane >> 3) & 1) * 8;
    const int lchunk = lane >> 4;
    const uint32_t aAddrBase = sb + SM_A + (m0 + lrow) * PITCHB + lchunk * 16;
    const uint4* wfl = g_wF + lane;

    // gather lane mapping: c4 = lane&15 (contiguous channels), two px/iter
    const int gc4 = lane & 15;
    const int gpx = lane >> 4;        // 0 or 1
    const float* cb = Tb + gc4 * 4;
    char* gAddrBase = smem + SM_A + m0 * PITCHB + gc4 * 8;

    // gather one tap's 32 rows into buffer `buf`
    auto gather_tap = [&](int tap, int buf) {
        char* dst = gAddrBase + buf * ABUF;
        #pragma unroll
        for (int iter = 0; iter < 16; ++iter) {
            int pxl = gpx + iter * 2;
            int e   = tap * TILE_PX + m0 + pxl;
            uint32_t pk = s_idx[e];
            float4   ww = s_wt[e];

            int i00 = pk & 0x3FFF;
            int dx  = (pk >> 14) & 1;
            int i01 = i00 + dx;
            int i10 = i00 + ((pk >> 15) & 1) * W_;
            int i11 = i10 + dx;

            float4 p00 = *(const float4*)(cb + (size_t)i00 * C_);
            float4 p01 = *(const float4*)(cb + (size_t)i01 * C_);
            float4 p10 = *(const float4*)(cb + (size_t)i10 * C_);
            float4 p11 = *(const float4*)(cb + (size_t)i11 * C_);

            float v0 = ww.x*p00.x + ww.y*p01.x + ww.z*p10.x + ww.w*p11.x;
            float v1 = ww.x*p00.y + ww.y*p01.y + ww.z*p10.y + ww.w*p11.y;
            float v2 = ww.x*p00.z + ww.y*p01.z + ww.z*p10.z + ww.w*p11.z;
            float v3 = ww.x*p00.w + ww.y*p01.w + ww.z*p10.w + ww.w*p11.w;

            uint32_t h01 = pack_f16x2(v0, v1);
            uint32_t h23 = pack_f16x2(v2, v3);
            *(uint2*)(dst + pxl * PITCHB) = make_uint2(h01, h23);
        }
    };

    // prologue: fill buffer 0 with tap 0
    gather_tap(0, 0);
    __syncwarp();

    #pragma unroll 1
    for (int tap = 0; tap < K_; ++tap) {
        const int buf = tap & 1;

        // ---- issue next tap's gather first (into buf^1): its LDGs fly
        //      while the MMAs below execute. No dependency between them. ---
        if (tap + 1 < K_) gather_tap(tap + 1, buf ^ 1);

        // ---- MMA on current buffer --------------------------------------
        const uint32_t aAddr0 = aAddrBase + buf * ABUF;
        const uint32_t aAddr1 = aAddr0 + 16 * PITCHB;
        const uint4* wft = wfl + tap * 1024;
        #pragma unroll
        for (int ks = 0; ks < 4; ++ks) {
            uint32_t a00, a01, a02, a03, a10, a11, a12, a13;
            LDMX4(a00, a01, a02, a03, aAddr0 + ks * 32);
            LDMX4(a10, a11, a12, a13, aAddr1 + ks * 32);
            const uint4* wfp = wft + ks * 256;

            #pragma unroll
            for (int nt = 0; nt < 8; ++nt) {
                uint4 bw = wfp[nt * 32];
                MMA_F16(acc[0][nt], a00, a01, a02, a03, bw.x, bw.y);
                MMA_F16(acc[0][nt], a00, a01, a02, a03, bw.z, bw.w);
                MMA_F16(acc[1][nt], a10, a11, a12, a13, bw.x, bw.y);
                MMA_F16(acc[1][nt], a10, a11, a12, a13, bw.z, bw.w);
            }
        }

        __syncwarp();   // next buffer's stores complete before its ldmatrix
    }

    // ---- epilogue: D frags -> out[b][o][q] + bias ------------------------
    float* ob = out + (size_t)b * O_ * Q_;
    #pragma unroll
    for (int mf = 0; mf < 2; ++mf) {
        int px0 = qbase + m0 + mf * 16 + (lane >> 2);
        #pragma unroll
        for (int nt = 0; nt < 8; ++nt) {
            int o0 = nt * 8 + 2 * (lane & 3);
            int o1 = o0 + 1;
            float b0 = s_bias[o0];
            float b1 = s_bias[o1];
            ob[(size_t)o0 * Q_ + px0]     = acc[mf][nt][0] + b0;
            ob[(size_t)o1 * Q_ + px0]     = acc[mf][nt][1] + b1;
            ob[(size_t)o0 * Q_ + px0 + 8] = acc[mf][nt][2] + b0;
            ob[(size_t)o1 * Q_ + px0 + 8] = acc[mf][nt][3] + b1;
        }
    }
}

// ---------------------------------------------------------------------------
extern "C" void kernel_launch(void* const* d_in, const int* in_sizes, int n_in,
                              void* d_out, int out_size)
{
    const float* input  = (const float*)d_in[0];  // [8,64,96,96]
    const float* offset = (const float*)d_in[1];  // [8,18,96,96]
    const float* mask   = (const float*)d_in[2];  // [8,9,96,96]
    const float* weight = (const float*)d_in[3];  // [64,64,3,3]
    const float* bias   = (const float*)d_in[4];  // [64]
    float* out = (float*)d_out;                   // [8,64,96,96]

    static int init_done = 0;
    if (!init_done) {
        cudaFuncSetAttribute(dcn_mma_kernel,
                             cudaFuncAttributeMaxDynamicSharedMemorySize,
                             SM_TOTAL);
        init_done = 1;
    }

    prep_kernel<<<B_ * (HW_ / 32) + 36, 256>>>(input, weight);
    dcn_mma_kernel<<<NTILES, THREADS, SM_TOTAL>>>(offset, mask, bias, out);
}

// round 16
// speedup vs baseline: 1.4277x; 1.4277x over previous
#include <cuda_runtime.h>
#include <cuda_fp16.h>
#include <cstdint>

// ---------------------------------------------------------------- shapes
#define B_   8
#define C_   64
#define H_   96
#define W_   96
#define O_   64
#define K_   9
#define HW_  (H_ * W_)        // 9216
#define Q_   HW_

#define TILE_PX 128
#define NTILES  (B_ * Q_ / TILE_PX)   // 576
#define THREADS 256                   // 8 warps = 4 pairs x 32 px
#define PITCHB  144                   // A row pitch bytes (128 data + 16 pad)

// ---------------------------------------------------------------- smem map (bytes)
#define SM_BIAS  0                        // float[64]
#define SM_IDX   256                      // uint32[9*128] = 4608
#define SM_WT    4864                     // float4[9*128] = 18432
#define SM_A     23296                    // 128 * 144 = 18432
#define SM_TOTAL 41728                    // < 48 KB

// ---------------------------------------------------------------- global scratch
__device__ float g_inT[(size_t)B_ * HW_ * C_];   // NHWC input (~18.9 MB)
__device__ uint4 g_wF[K_ * 4 * 8 * 32];          // B frags [tap][ks][nt][lane]
                                                 // = {bh0, bh1, bl0, bl1}

// ---------------------------------------------------------------- helpers
__device__ __forceinline__ uint32_t smem_u32(const void* p) {
    uint32_t a;
    asm("{ .reg .u64 t; cvta.to.shared.u64 t, %1; cvt.u32.u64 %0, t; }"
        : "=r"(a) : "l"(p));
    return a;
}

// packs: low half = cvt(lo), high half = cvt(hi)
__device__ __forceinline__ uint32_t pack_f16x2(float lo, float hi) {
    uint32_t r;
    asm("cvt.rn.f16x2.f32 %0, %1, %2;" : "=r"(r) : "f"(hi), "f"(lo));
    return r;
}

#define MMA_F16(d, a0, a1, a2, a3, b0, b1)                                    \
    asm volatile(                                                             \
        "mma.sync.aligned.m16n8k16.row.col.f32.f16.f16.f32 "                  \
        "{%0,%1,%2,%3}, {%4,%5,%6,%7}, {%8,%9}, {%0,%1,%2,%3};"               \
        : "+f"((d)[0]), "+f"((d)[1]), "+f"((d)[2]), "+f"((d)[3])              \
        : "r"(a0), "r"(a1), "r"(a2), "r"(a3), "r"(b0), "r"(b1))

#define LDMX4(r0, r1, r2, r3, addr)                                           \
    asm volatile(                                                             \
        "ldmatrix.sync.aligned.m8n8.x4.shared.b16 {%0,%1,%2,%3}, [%4];"       \
        : "=r"(r0), "=r"(r1), "=r"(r2), "=r"(r3) : "r"(addr))

#define BAR_SYNC(id)                                                          \
    asm volatile("bar.sync %0, 64;" :: "r"(id) : "memory")

// ---------------------------------------------------------------------------
// Prepass: NCHW -> NHWC input transpose + weight hi/lo fp16 fragment build.
// ---------------------------------------------------------------------------
__global__ __launch_bounds__(256) void prep_kernel(
    const float* __restrict__ in,    // [B][C][H][W]
    const float* __restrict__ wgt)   // [O][C][3][3]
{
    int blk = blockIdx.x;
    if (blk >= B_ * (HW_ / 32)) {                 // 36 weight-fragment blocks
        int idx = (blk - B_ * (HW_ / 32)) * 256 + threadIdx.x;   // 0..9215
        int lane = idx & 31;
        int nt   = (idx >> 5) & 7;
        int ks   = (idx >> 8) & 3;
        int tap  = idx >> 10;
        int n  = nt * 8 + (lane >> 2);
        int c0 = ks * 16 + (lane & 3) * 2;

        float w0 = wgt[n * 576 + (c0)     * 9 + tap];
        float w1 = wgt[n * 576 + (c0 + 1) * 9 + tap];
        float w8 = wgt[n * 576 + (c0 + 8) * 9 + tap];
        float w9 = wgt[n * 576 + (c0 + 9) * 9 + tap];

        float r0 = w0 - __half2float(__float2half_rn(w0));
        float r1 = w1 - __half2float(__float2half_rn(w1));
        float r8 = w8 - __half2float(__float2half_rn(w8));
        float r9 = w9 - __half2float(__float2half_rn(w9));

        uint4 f;
        f.x = pack_f16x2(w0, w1);   // bh0
        f.y = pack_f16x2(w8, w9);   // bh1
        f.z = pack_f16x2(r0, r1);   // bl0
        f.w = pack_f16x2(r8, r9);   // bl1
        g_wF[idx] = f;
        return;
    }
    __shared__ float s[64][33];
    int b   = blk / (HW_ / 32);
    int hw0 = (blk % (HW_ / 32)) * 32;
    for (int i = threadIdx.x; i < 64 * 32; i += 256) {
        int c = i >> 5, hw = i & 31;
        s[c][hw] = in[((size_t)(b * C_ + c)) * HW_ + hw0 + hw];
    }
    __syncthreads();
    for (int i = threadIdx.x; i < 64 * 32; i += 256) {
        int hw = i >> 6, c = i & 63;
        g_inT[((size_t)(b * HW_ + hw0 + hw)) * C_ + c] = s[c][hw];
    }
}

// ---------------------------------------------------------------------------
// Main fused kernel — 8 warps = 4 pairs; each pair owns 32 px.
// Pair: co-gather A tile (even warp c0-31, odd c32-63), bar.sync(pair),
// then each warp MMAs its own 4 n-tiles (disjoint outputs, no reduction).
// ---------------------------------------------------------------------------
__global__ __launch_bounds__(256, 3) void dcn_mma_kernel(
    const float* __restrict__ offset,  // [B][18][96][96]
    const float* __restrict__ mask,    // [B][9][96][96]
    const float* __restrict__ bias,    // [64]
    float* __restrict__ out)           // [B][64][96][96]
{
    extern __shared__ char smem[];
    float*    s_bias = (float*)(smem + SM_BIAS);
    uint32_t* s_idx  = (uint32_t*)(smem + SM_IDX);
    float4*   s_wt   = (float4*)(smem + SM_WT);

    const uint32_t sb = smem_u32(smem);
    const int tid  = threadIdx.x;
    const int lane = tid & 31;
    const int wid  = tid >> 5;                           // 0..7
    const int pair = wid >> 1;                           // 0..3
    const int half = wid & 1;                            // 0 = c0-31, 1 = c32-63
    const int m0   = pair * 32;                          // pair's 32 pixel rows
    const int b     = blockIdx.x / (Q_ / TILE_PX);       // /72
    const int qbase = (blockIdx.x % (Q_ / TILE_PX)) * TILE_PX;

    if (tid < 64) s_bias[tid] = bias[tid];

    const float* Tb = g_inT + (size_t)b * HW_ * C_;

    // ---- Phase 0: coords, taps split by parity across the pair -----------
    for (int tap = half; tap < K_; tap += 2) {
        int q  = qbase + m0 + lane;
        int ho = q / W_;
        int wo = q - ho * W_;
        int ky = tap / 3;
        int kx = tap - ky * 3;

        float offy = offset[((size_t)(b * 2 * K_ + 2 * tap)) * Q_ + q];
        float offx = offset[((size_t)(b * 2 * K_ + 2 * tap + 1)) * Q_ + q];
        float m    = mask[((size_t)(b * K_ + tap)) * Q_ + q];

        float y = (float)(ho - 1 + ky) + offy;
        float x = (float)(wo - 1 + kx) + offx;
        float y0f = floorf(y), x0f = floorf(x);
        int y0 = (int)y0f, x0 = (int)x0f;
        int y1 = y0 + 1,   x1 = x0 + 1;
        float wy = y - y0f, wx = x - x0f;

        float vy0 = (y0 >= 0 && y0 < H_) ? 1.0f : 0.0f;
        float vy1 = (y1 >= 0 && y1 < H_) ? 1.0f : 0.0f;
        float vx0 = (x0 >= 0 && x0 < W_) ? 1.0f : 0.0f;
        float vx1 = (x1 >= 0 && x1 < W_) ? 1.0f : 0.0f;

        float w00 = (1.0f - wy) * (1.0f - wx) * m * vy0 * vx0;
        float w01 = (1.0f - wy) * wx          * m * vy0 * vx1;
        float w10 = wy          * (1.0f - wx) * m * vy1 * vx0;
        float w11 = wy          * wx          * m * vy1 * vx1;

        int y0c = min(max(y0, 0), H_ - 1);
        int y1c = min(max(y1, 0), H_ - 1);
        int x0c = min(max(x0, 0), W_ - 1);
        int x1c = min(max(x1, 0), W_ - 1);

        // pack: i00 (14b) | dx<<14 | dy<<15
        uint32_t pk = (uint32_t)(y0c * W_ + x0c)
                    | ((uint32_t)(x1c - x0c) << 14)
                    | ((uint32_t)(y1c - y0c) << 15);

        int e = tap * TILE_PX + m0 + lane;
        s_idx[e] = pk;
        s_wt[e]  = make_float4(w00, w01, w10, w11);
    }
    __syncthreads();   // coords + bias visible to both warps of each pair

    // fragment accumulators: 2 m-frags x 4 n-tiles x 4 regs (32 floats)
    float acc[2][4][4];
    #pragma unroll
    for (int mf = 0; mf < 2; ++mf)
        #pragma unroll
        for (int j = 0; j < 4; ++j)
            #pragma unroll
            for (int r = 0; r < 4; ++r) acc[mf][j][r] = 0.0f;

    const int lrow   = (lane & 7) + ((lane >> 3) & 1) * 8;
    const int lchunk = lane >> 4;
    const uint32_t aAddr0 = sb + SM_A + (m0 + lrow) * PITCHB + lchunk * 16;
    const uint32_t aAddr1 = aAddr0 + 16 * PITCHB;
    const uint4* wfl = g_wF + lane;
    const int ntbase = half * 4;

    // gather lane mapping: warp covers its 8 c4-groups (32 channels)
    const int gc4 = half * 8 + (lane & 7);   // c4 group 0..15
    const int gpx = lane >> 3;               // 0..3
    const float* cb = Tb + gc4 * 4;

    for (int tap = 0; tap < K_; ++tap) {
        // ---- gather pair's 32 rows, this warp's channel half ------------
        #pragma unroll
        for (int iter = 0; iter < 8; ++iter) {
            int pxl = gpx + iter * 4;
            int e   = tap * TILE_PX + m0 + pxl;
            uint32_t pk = s_idx[e];
            float4   ww = s_wt[e];

            int i00 = pk & 0x3FFF;
            int dx  = (pk >> 14) & 1;
            int i01 = i00 + dx;
            int i10 = i00 + ((pk >> 15) & 1) * W_;
            int i11 = i10 + dx;

            float4 p00 = *(const float4*)(cb + (size_t)i00 * C_);
            float4 p01 = *(const float4*)(cb + (size_t)i01 * C_);
            float4 p10 = *(const float4*)(cb + (size_t)i10 * C_);
            float4 p11 = *(const float4*)(cb + (size_t)i11 * C_);

            float v0 = ww.x*p00.x + ww.y*p01.x + ww.z*p10.x + ww.w*p11.x;
            float v1 = ww.x*p00.y + ww.y*p01.y + ww.z*p10.y + ww.w*p11.y;
            float v2 = ww.x*p00.z + ww.y*p01.z + ww.z*p10.z + ww.w*p11.z;
            float v3 = ww.x*p00.w + ww.y*p01.w + ww.z*p10.w + ww.w*p11.w;

            uint32_t h01 = pack_f16x2(v0, v1);
            uint32_t h23 = pack_f16x2(v2, v3);
            *(uint2*)(smem + SM_A + (m0 + pxl) * PITCHB + gc4 * 8) =
                make_uint2(h01, h23);
        }

        BAR_SYNC(1 + pair);   // pair's A tile complete

        // ---- MMA: this warp's 4 n-tiles over all 4 k-steps --------------
        const uint4* wft = wfl + tap * 1024;
        #pragma unroll
        for (int ks = 0; ks < 4; ++ks) {
            uint32_t a00, a01, a02, a03, a10, a11, a12, a13;
            LDMX4(a00, a01, a02, a03, aAddr0 + ks * 32);
            LDMX4(a10, a11, a12, a13, aAddr1 + ks * 32);
            const uint4* wfp = wft + ks * 256;

            #pragma unroll
            for (int j = 0; j < 4; ++j) {
                uint4 bw = wfp[(ntbase + j) * 32];
                MMA_F16(acc[0][j], a00, a01, a02, a03, bw.x, bw.y);
                MMA_F16(acc[0][j], a00, a01, a02, a03, bw.z, bw.w);
                MMA_F16(acc[1][j], a10, a11, a12, a13, bw.x, bw.y);
                MMA_F16(acc[1][j], a10, a11, a12, a13, bw.z, bw.w);
            }
        }

        BAR_SYNC(1 + pair);   // both warps done reading A before overwrite
    }

    // ---- epilogue: D frags -> out[b][o][q] + bias ------------------------
    float* ob = out + (size_t)b * O_ * Q_;
    #pragma unroll
    for (int mf = 0; mf < 2; ++mf) {
        int px0 = qbase + m0 + mf * 16 + (lane >> 2);
        #pragma unroll
        for (int j = 0; j < 4; ++j) {
            int o0 = (ntbase + j) * 8 + 2 * (lane & 3);
            int o1 = o0 + 1;
            float b0 = s_bias[o0];
            float b1 = s_bias[o1];
            ob[(size_t)o0 * Q_ + px0]     = acc[mf][j][0] + b0;
            ob[(size_t)o1 * Q_ + px0]     = acc[mf][j][1] + b1;
            ob[(size_t)o0 * Q_ + px0 + 8] = acc[mf][j][2] + b0;
            ob[(size_t)o1 * Q_ + px0 + 8] = acc[mf][j][3] + b1;
        }
    }
}

// ---------------------------------------------------------------------------
extern "C" void kernel_launch(void* const* d_in, const int* in_sizes, int n_in,
                              void* d_out, int out_size)
{
    const float* input  = (const float*)d_in[0];  // [8,64,96,96]
    const float* offset = (const float*)d_in[1];  // [8,18,96,96]
    const float* mask   = (const float*)d_in[2];  // [8,9,96,96]
    const float* weight = (const float*)d_in[3];  // [64,64,3,3]
    const float* bias   = (const float*)d_in[4];  // [64]
    float* out = (float*)d_out;                   // [8,64,96,96]

    prep_kernel<<<B_ * (HW_ / 32) + 36, 256>>>(input, weight);
    dcn_mma_kernel<<<NTILES, THREADS, SM_TOTAL>>>(offset, mask, bias, out);
}

// round 17
// speedup vs baseline: 2.1857x; 1.5309x over previous
#include <cuda_runtime.h>
#include <cuda_fp16.h>
#include <cstdint>

// ---------------------------------------------------------------- shapes
#define B_   8
#define C_   64
#define H_   96
#define W_   96
#define O_   64
#define K_   9
#define HW_  (H_ * W_)        // 9216
#define Q_   HW_

#define TILE_PX 128
#define NTILES  (B_ * Q_ / TILE_PX)   // 576
#define THREADS 128                   // 4 warps x 32 px each
#define PITCHB  144                   // A row pitch bytes (128 data + 16 pad)

// ---------------------------------------------------------------- smem map (bytes)
#define SM_BIAS  0                        // float[64]
#define SM_IDX   256                      // uint32[9*128] = 4608
#define SM_WTP   4864                     // uint2[9*128]  = 9216 (packed half wts)
#define SM_A     14080                    // 128 * 144 = 18432
#define SM_TOTAL 32512                    // < 48 KB

// ---------------------------------------------------------------- global scratch
__device__ __half g_inT[(size_t)B_ * HW_ * C_];  // NHWC fp16 input (~9.4 MB)
__device__ uint4  g_wF[K_ * 4 * 8 * 32];         // B frags [tap][ks][nt][lane]
                                                 // = {bh0, bh1, bl0, bl1}

// ---------------------------------------------------------------- helpers
__device__ __forceinline__ uint32_t smem_u32(const void* p) {
    uint32_t a;
    asm("{ .reg .u64 t; cvta.to.shared.u64 t, %1; cvt.u32.u64 %0, t; }"
        : "=r"(a) : "l"(p));
    return a;
}

// packs: low half = cvt(lo), high half = cvt(hi)
__device__ __forceinline__ uint32_t pack_f16x2(float lo, float hi) {
    uint32_t r;
    asm("cvt.rn.f16x2.f32 %0, %1, %2;" : "=r"(r) : "f"(hi), "f"(lo));
    return r;
}

#define MMA_F16(d, a0, a1, a2, a3, b0, b1)                                    \
    asm volatile(                                                             \
        "mma.sync.aligned.m16n8k16.row.col.f32.f16.f16.f32 "                  \
        "{%0,%1,%2,%3}, {%4,%5,%6,%7}, {%8,%9}, {%0,%1,%2,%3};"               \
        : "+f"((d)[0]), "+f"((d)[1]), "+f"((d)[2]), "+f"((d)[3])              \
        : "r"(a0), "r"(a1), "r"(a2), "r"(a3), "r"(b0), "r"(b1))

#define LDMX4(r0, r1, r2, r3, addr)                                           \
    asm volatile(                                                             \
        "ldmatrix.sync.aligned.m8n8.x4.shared.b16 {%0,%1,%2,%3}, [%4];"       \
        : "=r"(r0), "=r"(r1), "=r"(r2), "=r"(r3) : "r"(addr))

// ---------------------------------------------------------------------------
// Prepass: NCHW -> NHWC fp16 transpose + weight hi/lo fp16 fragment build.
// ---------------------------------------------------------------------------
__global__ __launch_bounds__(256) void prep_kernel(
    const float* __restrict__ in,    // [B][C][H][W]
    const float* __restrict__ wgt)   // [O][C][3][3]
{
    int blk = blockIdx.x;
    if (blk >= B_ * (HW_ / 32)) {                 // 36 weight-fragment blocks
        int idx = (blk - B_ * (HW_ / 32)) * 256 + threadIdx.x;   // 0..9215
        int lane = idx & 31;
        int nt   = (idx >> 5) & 7;
        int ks   = (idx >> 8) & 3;
        int tap  = idx >> 10;
        int n  = nt * 8 + (lane >> 2);
        int c0 = ks * 16 + (lane & 3) * 2;

        float w0 = wgt[n * 576 + (c0)     * 9 + tap];
        float w1 = wgt[n * 576 + (c0 + 1) * 9 + tap];
        float w8 = wgt[n * 576 + (c0 + 8) * 9 + tap];
        float w9 = wgt[n * 576 + (c0 + 9) * 9 + tap];

        float r0 = w0 - __half2float(__float2half_rn(w0));
        float r1 = w1 - __half2float(__float2half_rn(w1));
        float r8 = w8 - __half2float(__float2half_rn(w8));
        float r9 = w9 - __half2float(__float2half_rn(w9));

        uint4 f;
        f.x = pack_f16x2(w0, w1);   // bh0
        f.y = pack_f16x2(w8, w9);   // bh1
        f.z = pack_f16x2(r0, r1);   // bl0
        f.w = pack_f16x2(r8, r9);   // bl1
        g_wF[idx] = f;
        return;
    }
    __shared__ float s[64][33];
    int b   = blk / (HW_ / 32);
    int hw0 = (blk % (HW_ / 32)) * 32;
    for (int i = threadIdx.x; i < 64 * 32; i += 256) {
        int c = i >> 5, hw = i & 31;
        s[c][hw] = in[((size_t)(b * C_ + c)) * HW_ + hw0 + hw];
    }
    __syncthreads();
    for (int i = threadIdx.x; i < 64 * 32; i += 256) {
        int hw = i >> 6, c = i & 63;
        g_inT[((size_t)(b * HW_ + hw0 + hw)) * C_ + c] =
            __float2half(s[c][hw]);
    }
}

// ---------------------------------------------------------------------------
// Main fused kernel — 4 warps/block, 32 px per warp, warp-synchronous tap
// loop. fp16 NHWC gather with packed half2 bilinear (half the L1 bytes).
// ---------------------------------------------------------------------------
__global__ __launch_bounds__(128) void dcn_mma_kernel(
    const float* __restrict__ offset,  // [B][18][96][96]
    const float* __restrict__ mask,    // [B][9][96][96]
    const float* __restrict__ bias,    // [64]
    float* __restrict__ out)           // [B][64][96][96]
{
    extern __shared__ char smem[];
    float*    s_bias = (float*)(smem + SM_BIAS);
    uint32_t* s_idx  = (uint32_t*)(smem + SM_IDX);
    uint2*    s_wtp  = (uint2*)(smem + SM_WTP);

    const uint32_t sb = smem_u32(smem);
    const int tid  = threadIdx.x;
    const int lane = tid & 31;
    const int wid  = tid >> 5;                           // 0..3
    const int m0   = wid * 32;                           // warp's 32 pixel rows
    const int b     = blockIdx.x / (Q_ / TILE_PX);       // /72
    const int qbase = (blockIdx.x % (Q_ / TILE_PX)) * TILE_PX;

    if (tid < 64) s_bias[tid] = bias[tid];

    const __half* Tb = g_inT + (size_t)b * HW_ * C_;

    // ---- Phase 0: per-warp coords, 9 taps x 32 px (1 task/lane/tap) ------
    #pragma unroll
    for (int tap = 0; tap < K_; ++tap) {
        int q  = qbase + m0 + lane;
        int ho = q / W_;
        int wo = q - ho * W_;
        int ky = tap / 3;
        int kx = tap - ky * 3;

        float offy = offset[((size_t)(b * 2 * K_ + 2 * tap)) * Q_ + q];
        float offx = offset[((size_t)(b * 2 * K_ + 2 * tap + 1)) * Q_ + q];
        float m    = mask[((size_t)(b * K_ + tap)) * Q_ + q];

        float y = (float)(ho - 1 + ky) + offy;
        float x = (float)(wo - 1 + kx) + offx;
        float y0f = floorf(y), x0f = floorf(x);
        int y0 = (int)y0f, x0 = (int)x0f;
        int y1 = y0 + 1,   x1 = x0 + 1;
        float wy = y - y0f, wx = x - x0f;

        float vy0 = (y0 >= 0 && y0 < H_) ? 1.0f : 0.0f;
        float vy1 = (y1 >= 0 && y1 < H_) ? 1.0f : 0.0f;
        float vx0 = (x0 >= 0 && x0 < W_) ? 1.0f : 0.0f;
        float vx1 = (x1 >= 0 && x1 < W_) ? 1.0f : 0.0f;

        float w00 = (1.0f - wy) * (1.0f - wx) * m * vy0 * vx0;
        float w01 = (1.0f - wy) * wx          * m * vy0 * vx1;
        float w10 = wy          * (1.0f - wx) * m * vy1 * vx0;
        float w11 = wy          * wx          * m * vy1 * vx1;

        int y0c = min(max(y0, 0), H_ - 1);
        int y1c = min(max(y1, 0), H_ - 1);
        int x0c = min(max(x0, 0), W_ - 1);
        int x1c = min(max(x1, 0), W_ - 1);

        // pack: i00 (14b) | dx<<14 | dy<<15
        uint32_t pk = (uint32_t)(y0c * W_ + x0c)
                    | ((uint32_t)(x1c - x0c) << 14)
                    | ((uint32_t)(y1c - y0c) << 15);

        int e = tap * TILE_PX + m0 + lane;
        s_idx[e] = pk;
        s_wtp[e] = make_uint2(pack_f16x2(w00, w01), pack_f16x2(w10, w11));
    }
    __syncthreads();   // bias visible (coords are warp-local)

    // fragment accumulators: 2 m-frags x 8 n-tiles x 4 regs
    float acc[2][8][4];
    #pragma unroll
    for (int mf = 0; mf < 2; ++mf)
        #pragma unroll
        for (int nt = 0; nt < 8; ++nt)
            #pragma unroll
            for (int j = 0; j < 4; ++j) acc[mf][nt][j] = 0.0f;

    const int lrow   = (lane & 7) + ((lane >> 3) & 1) * 8;
    const int lchunk = lane >> 4;
    const uint32_t aAddr0 = sb + SM_A + (m0 + lrow) * PITCHB + lchunk * 16;
    const uint32_t aAddr1 = aAddr0 + 16 * PITCHB;
    const uint4* wfl = g_wF + lane;

    // gather lane mapping: c8 = lane&7 (8-channel group), 4 px per iter
    const int gc8 = lane & 7;
    const int gpx = lane >> 3;        // 0..3
    const __half* cb = Tb + gc8 * 8;

    for (int tap = 0; tap < K_; ++tap) {
        // ---- gather warp's 32 rows: 8 iters x 4 px ----------------------
        #pragma unroll
        for (int iter = 0; iter < 8; ++iter) {
            int pxl = gpx + iter * 4;
            int e   = tap * TILE_PX + m0 + pxl;
            uint32_t pk = s_idx[e];
            uint2    wp = s_wtp[e];

            int i00 = pk & 0x3FFF;
            int dx  = (pk >> 14) & 1;
            int i01 = i00 + dx;
            int i10 = i00 + ((pk >> 15) & 1) * W_;
            int i11 = i10 + dx;

            uint4 q00 = *(const uint4*)(cb + (size_t)i00 * C_);
            uint4 q01 = *(const uint4*)(cb + (size_t)i01 * C_);
            uint4 q10 = *(const uint4*)(cb + (size_t)i10 * C_);
            uint4 q11 = *(const uint4*)(cb + (size_t)i11 * C_);

            half2 hA = *(half2*)&wp.x;           // {w00, w01}
            half2 hB = *(half2*)&wp.y;           // {w10, w11}
            half2 w00 = __low2half2(hA);
            half2 w01 = __high2half2(hA);
            half2 w10 = __low2half2(hB);
            half2 w11 = __high2half2(hB);

            const half2* p00 = (const half2*)&q00;
            const half2* p01 = (const half2*)&q01;
            const half2* p10 = (const half2*)&q10;
            const half2* p11 = (const half2*)&q11;

            uint4 vout;
            uint32_t* vw = (uint32_t*)&vout;
            #pragma unroll
            for (int j = 0; j < 4; ++j) {
                half2 v = __hfma2(w00, p00[j],
                          __hfma2(w01, p01[j],
                          __hfma2(w10, p10[j],
                          __hmul2(w11, p11[j]))));
                vw[j] = *(uint32_t*)&v;
            }
            *(uint4*)(smem + SM_A + (m0 + pxl) * PITCHB + gc8 * 16) = vout;
        }

        __syncwarp();   // warp's A rows ready

        // ---- MMA: 4 k-steps x (2 A-ldm + 8 x (B LDG.128 + 4 MMA)) -------
        const uint4* wft = wfl + tap * 1024;
        #pragma unroll
        for (int ks = 0; ks < 4; ++ks) {
            uint32_t a00, a01, a02, a03, a10, a11, a12, a13;
            LDMX4(a00, a01, a02, a03, aAddr0 + ks * 32);
            LDMX4(a10, a11, a12, a13, aAddr1 + ks * 32);
            const uint4* wfp = wft + ks * 256;

            #pragma unroll
            for (int nt = 0; nt < 8; ++nt) {
                uint4 bw = wfp[nt * 32];
                MMA_F16(acc[0][nt], a00, a01, a02, a03, bw.x, bw.y);
                MMA_F16(acc[0][nt], a00, a01, a02, a03, bw.z, bw.w);
                MMA_F16(acc[1][nt], a10, a11, a12, a13, bw.x, bw.y);
                MMA_F16(acc[1][nt], a10, a11, a12, a13, bw.z, bw.w);
            }
        }

        __syncwarp();   // ldmatrix reads done before next tap overwrites
    }

    // ---- epilogue: D frags -> out[b][o][q] + bias ------------------------
    float* ob = out + (size_t)b * O_ * Q_;
    #pragma unroll
    for (int mf = 0; mf < 2; ++mf) {
        int px0 = qbase + m0 + mf * 16 + (lane >> 2);
        #pragma unroll
        for (int nt = 0; nt < 8; ++nt) {
            int o0 = nt * 8 + 2 * (lane & 3);
            int o1 = o0 + 1;
            float b0 = s_bias[o0];
            float b1 = s_bias[o1];
            ob[(size_t)o0 * Q_ + px0]     = acc[mf][nt][0] + b0;
            ob[(size_t)o1 * Q_ + px0]     = acc[mf][nt][1] + b1;
            ob[(size_t)o0 * Q_ + px0 + 8] = acc[mf][nt][2] + b0;
            ob[(size_t)o1 * Q_ + px0 + 8] = acc[mf][nt][3] + b1;
        }
    }
}

// ---------------------------------------------------------------------------
extern "C" void kernel_launch(void* const* d_in, const int* in_sizes, int n_in,
                              void* d_out, int out_size)
{
    const float* input  = (const float*)d_in[0];  // [8,64,96,96]
    const float* offset = (const float*)d_in[1];  // [8,18,96,96]
    const float* mask   = (const float*)d_in[2];  // [8,9,96,96]
    const float* weight = (const float*)d_in[3];  // [64,64,3,3]
    const float* bias   = (const float*)d_in[4];  // [64]
    float* out = (float*)d_out;                   // [8,64,96,96]

    prep_kernel<<<B_ * (HW_ / 32) + 36, 256>>>(input, weight);
    dcn_mma_kernel<<<NTILES, THREADS, SM_TOTAL>>>(offset, mask, bias, out);
}